// round 17
// baseline (speedup 1.0000x reference)
#include <cuda_runtime.h>
#include <cuda_bf16.h>
#include <cstdint>

#define B_  32
#define N_  1024
#define D_  128
#define NDF (N_*D_)          // 131072 per batch per tensor
#define TOT (B_*N_*D_)       // 4194304
#define NBUCK 2048           // 11-bit monotone-key prefix buckets

// ---------------- device scratch (zero-init == ready state; all self-cleaning) ----------------
__device__ float    g_normP[B_*N_];
__device__ float    g_normT[B_*N_];
__device__ unsigned g_m1[B_*N_];       // max of (0x7F800000 - bits(d^2)); 0 == +inf
__device__ unsigned g_m2[N_*N_];
__device__ double   g_mae, g_s1, g_s2;
__device__ double   g_emd[B_];
__device__ unsigned g_cntP[B_*NBUCK];
__device__ unsigned g_cntG[B_*NBUCK];
__device__ float    g_sumP[B_*NBUCK];
__device__ float    g_sumG[B_*NBUCK];
__device__ unsigned g_bfP[TOT/2];      // bf16x2 packed pred
__device__ unsigned g_bfG[TOT/2];      // bf16x2 packed target
__device__ unsigned g_done;            // k_post completion counter (self-resets)

// ---------------- helpers ----------------
__device__ __forceinline__ unsigned pack_bf16x2(float lo, float hi) {
    unsigned r;
    asm("cvt.rn.bf16x2.f32 %0, %1, %2;" : "=r"(r) : "f"(hi), "f"(lo));
    return r;
}
__device__ __forceinline__ float bf_lo(unsigned u) { return __uint_as_float(u << 16); }
__device__ __forceinline__ float bf_hi(unsigned u) { return __uint_as_float(u & 0xFFFF0000u); }

__device__ __forceinline__ void mma_bf16(float* c, const unsigned* a, const unsigned* b) {
    asm volatile(
        "mma.sync.aligned.m16n8k16.row.col.f32.bf16.bf16.f32 "
        "{%0,%1,%2,%3}, {%4,%5,%6,%7}, {%8,%9}, {%0,%1,%2,%3};\n"
        : "+f"(c[0]), "+f"(c[1]), "+f"(c[2]), "+f"(c[3])
        : "r"(a[0]), "r"(a[1]), "r"(a[2]), "r"(a[3]), "r"(b[0]), "r"(b[1]));
}
__device__ __forceinline__ void ldsm_x4(unsigned* r, uint32_t addr) {
    asm volatile("ldmatrix.sync.aligned.m8n8.x4.shared.b16 {%0,%1,%2,%3}, [%4];"
        : "=r"(r[0]), "=r"(r[1]), "=r"(r[2]), "=r"(r[3]) : "r"(addr));
}
__device__ __forceinline__ void cp_async8(uint32_t saddr, const void* g) {
    asm volatile("cp.async.ca.shared.global [%0], [%1], 8;" :: "r"(saddr), "l"(g));
}
__device__ __forceinline__ void cp_async4(uint32_t saddr, const void* g) {
    asm volatile("cp.async.ca.shared.global [%0], [%1], 4;" :: "r"(saddr), "l"(g));
}
#define CP_COMMIT()  asm volatile("cp.async.commit_group;")
#define CP_WAIT(n)   asm volatile("cp.async.wait_group %0;" :: "n"(n))

__device__ __forceinline__ float blockReduceSum(float v) {
    #pragma unroll
    for (int o = 16; o; o >>= 1) v += __shfl_xor_sync(0xffffffffu, v, o);
    __shared__ float sm[32];
    int lane = threadIdx.x & 31, w = threadIdx.x >> 5;
    int nw = (blockDim.x + 31) >> 5;
    if (lane == 0) sm[w] = v;
    __syncthreads();
    if (w == 0) {
        v = (lane < nw) ? sm[lane] : 0.f;
        #pragma unroll
        for (int o = 16; o; o >>= 1) v += __shfl_xor_sync(0xffffffffu, v, o);
    }
    return v;  // valid on thread 0
}
__device__ __forceinline__ unsigned keyenc(float v) {
    unsigned u = __float_as_uint(v);
    return (u & 0x80000000u) ? ~u : (u | 0x80000000u);
}
__device__ __forceinline__ float keydec(unsigned u) {
    unsigned bits = (u & 0x80000000u) ? (u ^ 0x80000000u) : ~u;
    return __uint_as_float(bits);
}
// negated-min encoding: larger == smaller d^2; 0 == +inf (matches static zero-init)
__device__ __forceinline__ unsigned minenc(float d2) {
    return 0x7F800000u - __float_as_uint(d2);
}
__device__ __forceinline__ float mindec(unsigned t) {
    return __uint_as_float(0x7F800000u - t);
}

// ---- fused MAE + bf16 conversion + norms + smem-privatized EMD histograms ----
// 512 blocks x 512 threads; block owns 64 rows of one batch. 32 KB smem -> high occupancy.
#define FUSED_SMEM (4*NBUCK*4)   // 32 KB

__global__ void __launch_bounds__(512)
k_fused(const float* __restrict__ pred, const float* __restrict__ target) {
    extern __shared__ unsigned sh[];
    unsigned* scP = sh;                 // [NBUCK]
    float*    ssP = (float*)(sh + NBUCK);
    unsigned* scG = sh + 2*NBUCK;
    float*    ssG = (float*)(sh + 3*NBUCK);

    const int t = threadIdx.x;
    const int lane = t & 31, w = t >> 5;          // 16 warps
    const int batch = blockIdx.x >> 4;
    const int chunk = blockIdx.x & 15;
    const int row0 = batch * N_ + chunk * 64;

    for (int i = t; i < NBUCK; i += 512) {
        scP[i] = 0u; ssP[i] = 0.f; scG[i] = 0u; ssG[i] = 0.f;
    }
    __syncthreads();

    uint2* bfP2 = reinterpret_cast<uint2*>(g_bfP);
    uint2* bfG2 = reinterpret_cast<uint2*>(g_bfG);

    float macc = 0.f;
    #pragma unroll
    for (int pass = 0; pass < 4; ++pass) {
        int row = row0 + pass*16 + w;
        float4 p  = reinterpret_cast<const float4*>(pred)[row*32 + lane];
        float4 tg = reinterpret_cast<const float4*>(target)[row*32 + lane];
        macc += fabsf(p.x-tg.x)+fabsf(p.y-tg.y)+fabsf(p.z-tg.z)+fabsf(p.w-tg.w);
        // bf16 scratch
        uint2 up, ug;
        up.x = pack_bf16x2(p.x, p.y);
        up.y = pack_bf16x2(p.z, p.w);
        ug.x = pack_bf16x2(tg.x, tg.y);
        ug.y = pack_bf16x2(tg.z, tg.w);
        bfP2[row*32 + lane] = up;
        bfG2[row*32 + lane] = ug;
        // norms of bf16-rounded values (consistent with chamfer MMA inputs)
        {
            float a0 = bf_lo(up.x), a1 = bf_hi(up.x), a2 = bf_lo(up.y), a3 = bf_hi(up.y);
            float b0 = bf_lo(ug.x), b1 = bf_hi(ug.x), b2 = bf_lo(ug.y), b3 = bf_hi(ug.y);
            float np = a0*a0 + a1*a1 + a2*a2 + a3*a3;
            float nt = b0*b0 + b1*b1 + b2*b2 + b3*b3;
            #pragma unroll
            for (int o = 16; o; o >>= 1) {
                np += __shfl_xor_sync(0xffffffffu, np, o);
                nt += __shfl_xor_sync(0xffffffffu, nt, o);
            }
            if (lane == 0) { g_normP[row] = np; g_normT[row] = nt; }
        }
        // histograms (exact f32 values; 11-bit prefix)
        atomicAdd(&scP[keyenc(p.x)  >> 21], 1u); atomicAdd(&ssP[keyenc(p.x)  >> 21], p.x);
        atomicAdd(&scP[keyenc(p.y)  >> 21], 1u); atomicAdd(&ssP[keyenc(p.y)  >> 21], p.y);
        atomicAdd(&scP[keyenc(p.z)  >> 21], 1u); atomicAdd(&ssP[keyenc(p.z)  >> 21], p.z);
        atomicAdd(&scP[keyenc(p.w)  >> 21], 1u); atomicAdd(&ssP[keyenc(p.w)  >> 21], p.w);
        atomicAdd(&scG[keyenc(tg.x) >> 21], 1u); atomicAdd(&ssG[keyenc(tg.x) >> 21], tg.x);
        atomicAdd(&scG[keyenc(tg.y) >> 21], 1u); atomicAdd(&ssG[keyenc(tg.y) >> 21], tg.y);
        atomicAdd(&scG[keyenc(tg.z) >> 21], 1u); atomicAdd(&ssG[keyenc(tg.z) >> 21], tg.z);
        atomicAdd(&scG[keyenc(tg.w) >> 21], 1u); atomicAdd(&ssG[keyenc(tg.w) >> 21], tg.w);
    }

    // MAE reduce
    #pragma unroll
    for (int o = 16; o; o >>= 1) macc += __shfl_xor_sync(0xffffffffu, macc, o);
    __shared__ float bsum;
    if (t == 0) bsum = 0.f;
    __syncthreads();
    if (lane == 0) atomicAdd(&bsum, macc);
    __syncthreads();
    if (t == 0) atomicAdd(&g_mae, (double)bsum);

    // merge populated buckets to global
    const size_t boff = (size_t)batch * NBUCK;
    for (int i = t; i < NBUCK; i += 512) {
        unsigned c = scP[i];
        if (c) { atomicAdd(&g_cntP[boff+i], c); atomicAdd(&g_sumP[boff+i], ssP[i]); }
        c = scG[i];
        if (c) { atomicAdd(&g_cntG[boff+i], c); atomicAdd(&g_sumG[boff+i], ssG[i]); }
    }
}

// ---- chamfer: bf16 MMA + ldmatrix + cp.async double buffering, single wave ----
#define TI 128
#define TJ 128
#define BB 16
#define SROW 68              // u32 stride/row: 272B == 4 banks (mod 32), LDSM conflict-free
#define ABUF (128*SROW)      // u32 per tile
#define CHAM_SMEM ((4*ABUF + 512) * 4)   // 2 bufs x (A+B) + 2 x 256 norm floats

__global__ void __launch_bounds__(512, 1)
k_chamfer() {
    extern __shared__ unsigned smem_u[];

    const int tid  = threadIdx.x;
    const int lane = tid & 31;
    const int warp = tid >> 5;           // 0..15
    const int wi = warp >> 2;            // 0..3
    const int wj = warp & 3;             // 0..3
    const int g  = lane >> 2;            // 0..7
    const int cc = lane & 3;             // 0..3

    const int i0 = blockIdx.x * TI;
    const int j0 = blockIdx.y * TJ;
    const int b0 = blockIdx.z * BB;

    const uint2* bfP2 = reinterpret_cast<const uint2*>(g_bfP);
    const uint2* bfG2 = reinterpret_cast<const uint2*>(g_bfG);

    uint32_t sbase = (uint32_t)__cvta_generic_to_shared(smem_u);

    // ldmatrix per-lane offsets (relative to tile start, bytes)
    uint32_t aOff[2], bOff[2];
    #pragma unroll
    for (int mt = 0; mt < 2; ++mt) {
        int row = wi*32 + mt*16 + (lane & 15);
        aOff[mt] = (row*SROW + (lane >> 4)*4) * 4;
    }
    #pragma unroll
    for (int p = 0; p < 2; ++p) {
        int q = lane >> 3;                                  // 0..3
        int jr = wj*32 + (p*2 + (q >> 1))*8 + (lane & 7);   // two n8 tiles per LDSM
        bOff[p] = (jr*SROW + (q & 1)*4) * 4;
    }

    // async tile loader: batch bi -> buffer buf
    auto issue_load = [&](int bi, int buf) {
        const int b = b0 + bi;
        uint32_t abase = sbase + (buf*2*ABUF) * 4;
        uint32_t bbase = abase + ABUF * 4;
        #pragma unroll
        for (int r = 0; r < 8; ++r) {
            int row = r*16 + warp;
            cp_async8(abase + (row*SROW + lane*2)*4, &bfP2[((size_t)b*N_ + i0 + row)*32 + lane]);
            cp_async8(bbase + (row*SROW + lane*2)*4, &bfG2[((size_t)b*N_ + j0 + row)*32 + lane]);
        }
        uint32_t nbase = sbase + (4*ABUF + buf*256) * 4;
        if (tid < 128)       cp_async4(nbase + tid*4, &g_normP[b*N_ + i0 + tid]);
        else if (tid < 256)  cp_async4(nbase + tid*4, &g_normT[b*N_ + j0 + (tid-128)]);
        CP_COMMIT();
    };

    float dmin[2][4][4];
    #pragma unroll
    for (int mt = 0; mt < 2; mt++)
        #pragma unroll
        for (int nt = 0; nt < 4; nt++)
            #pragma unroll
            for (int q = 0; q < 4; q++) dmin[mt][nt][q] = 3.4e38f;

    issue_load(0, 0);

    for (int bi = 0; bi < BB; ++bi) {
        const int b = b0 + bi;
        const int buf = bi & 1;
        if (bi + 1 < BB) { issue_load(bi + 1, (bi + 1) & 1); CP_WAIT(1); }
        else             { CP_WAIT(0); }
        __syncthreads();

        const uint32_t tilebase = sbase + (buf*2*ABUF)*4;
        const float* sNp = (const float*)(smem_u + 4*ABUF + buf*256);
        const float* sNt = sNp + 128;

        float acc[2][4][4];
        #pragma unroll
        for (int mt = 0; mt < 2; mt++)
            #pragma unroll
            for (int nt = 0; nt < 4; nt++)
                #pragma unroll
                for (int q = 0; q < 4; q++) acc[mt][nt][q] = 0.f;

        #pragma unroll
        for (int ks = 0; ks < 8; ++ks) {
            unsigned a[2][4], bf[2][4];
            ldsm_x4(a[0],  tilebase + aOff[0] + ks*32);
            ldsm_x4(a[1],  tilebase + aOff[1] + ks*32);
            ldsm_x4(bf[0], tilebase + ABUF*4 + bOff[0] + ks*32);
            ldsm_x4(bf[1], tilebase + ABUF*4 + bOff[1] + ks*32);
            #pragma unroll
            for (int mt = 0; mt < 2; ++mt)
                #pragma unroll
                for (int nt = 0; nt < 4; ++nt) {
                    unsigned bb[2] = { bf[nt>>1][(nt&1)*2], bf[nt>>1][(nt&1)*2 + 1] };
                    mma_bf16(acc[mt][nt], a[mt], bb);
                }
        }

        float nP[2][2];
        #pragma unroll
        for (int mt = 0; mt < 2; ++mt) {
            int r0 = wi*32 + mt*16 + g;
            nP[mt][0] = sNp[r0];
            nP[mt][1] = sNp[r0+8];
        }
        #pragma unroll
        for (int nt = 0; nt < 4; ++nt) {
            int cA = wj*32 + nt*8 + 2*cc;
            float nt0 = sNt[cA], nt1 = sNt[cA+1];
            float cm0 = 3.4e38f, cm1 = 3.4e38f;
            #pragma unroll
            for (int mt = 0; mt < 2; ++mt) {
                float s0 = fmaxf(fmaf(-2.f, acc[mt][nt][0], nP[mt][0] + nt0), 1e-12f);
                float s1 = fmaxf(fmaf(-2.f, acc[mt][nt][1], nP[mt][0] + nt1), 1e-12f);
                float s2 = fmaxf(fmaf(-2.f, acc[mt][nt][2], nP[mt][1] + nt0), 1e-12f);
                float s3 = fmaxf(fmaf(-2.f, acc[mt][nt][3], nP[mt][1] + nt1), 1e-12f);
                dmin[mt][nt][0] = fminf(dmin[mt][nt][0], s0);
                dmin[mt][nt][1] = fminf(dmin[mt][nt][1], s1);
                dmin[mt][nt][2] = fminf(dmin[mt][nt][2], s2);
                dmin[mt][nt][3] = fminf(dmin[mt][nt][3], s3);
                cm0 = fminf(cm0, fminf(s0, s2));
                cm1 = fminf(cm1, fminf(s1, s3));
            }
            #pragma unroll
            for (int o = 4; o <= 16; o <<= 1) {
                cm0 = fminf(cm0, __shfl_xor_sync(0xffffffffu, cm0, o));
                cm1 = fminf(cm1, __shfl_xor_sync(0xffffffffu, cm1, o));
            }
            if (g == 0) {
                atomicMax(&g_m1[b*N_ + j0 + cA],     minenc(cm0));
                atomicMax(&g_m1[b*N_ + j0 + cA + 1], minenc(cm1));
            }
        }
        __syncthreads();   // protect buffer reuse by next issue_load
    }

    #pragma unroll
    for (int mt = 0; mt < 2; ++mt) {
        int r0 = i0 + wi*32 + mt*16 + g;
        #pragma unroll
        for (int nt = 0; nt < 4; ++nt) {
            int cA = j0 + wj*32 + nt*8 + 2*cc;
            atomicMax(&g_m2[r0*N_ + cA],       minenc(dmin[mt][nt][0]));
            atomicMax(&g_m2[r0*N_ + cA + 1],   minenc(dmin[mt][nt][1]));
            atomicMax(&g_m2[(r0+8)*N_ + cA],   minenc(dmin[mt][nt][2]));
            atomicMax(&g_m2[(r0+8)*N_ + cA+1], minenc(dmin[mt][nt][3]));
        }
    }
}

// ---- post pass: EMD CDF (blocks 0..31, 2 buckets/thread), m1 sqrt-sum (32..39),
//      m2 sqrt-sum (40..287); last finishing block combines into out. Self-cleaning. ----
__global__ void __launch_bounds__(1024) k_post(float* __restrict__ out) {
    const int bx = blockIdx.x;
    const int t = threadIdx.x, lane = t & 31, w = t >> 5;
    if (bx < 32) {
        const int b = bx;
        unsigned* cp = g_cntP + (size_t)b * NBUCK;
        unsigned* cg = g_cntG + (size_t)b * NBUCK;
        float*    sp = g_sumP + (size_t)b * NBUCK;
        float*    sg = g_sumG + (size_t)b * NBUCK;
        uint2 cu2 = reinterpret_cast<uint2*>(cp)[t];
        uint2 cv2 = reinterpret_cast<uint2*>(cg)[t];
        float2 su2 = reinterpret_cast<float2*>(sp)[t];
        float2 sv2 = reinterpret_cast<float2*>(sg)[t];
        int cu[2] = {(int)cu2.x,(int)cu2.y};
        int cv[2] = {(int)cv2.x,(int)cv2.y};
        float su[2] = {su2.x,su2.y};
        float sv[2] = {sv2.x,sv2.y};
        int pre[2]; int tot = 0;
        #pragma unroll
        for (int j = 0; j < 2; ++j) { pre[j] = tot; tot += cu[j] - cv[j]; }
        __shared__ int wsum[32];
        int x = tot;
        #pragma unroll
        for (int o = 1; o < 32; o <<= 1) {
            int y = __shfl_up_sync(0xffffffffu, x, o);
            if (lane >= o) x += y;
        }
        if (lane == 31) wsum[w] = x;
        __syncthreads();
        if (w == 0) {
            int v = wsum[lane];
            #pragma unroll
            for (int o = 1; o < 32; o <<= 1) {
                int y = __shfl_up_sync(0xffffffffu, v, o);
                if (lane >= o) v += y;
            }
            wsum[lane] = v;
        }
        __syncthreads();
        int texcl = x - tot + (w ? wsum[w-1] : 0);
        double acc = 0.0;
        #pragma unroll
        for (int j = 0; j < 2; ++j) {
            int excl = texcl + pre[j];
            if (((cu[j] | cv[j]) != 0) || (excl != 0)) {
                unsigned kb = (unsigned)(t*2 + j) << 21;
                double L = (double)keydec(kb);
                double R = (double)keydec(kb + 0x200000u);
                acc += fabs((double)excl * (R - L)
                            + (double)cu[j] * R - (double)su[j]
                            - (double)cv[j] * R + (double)sv[j]);
            }
        }
        reinterpret_cast<uint2*>(cp)[t] = make_uint2(0,0);
        reinterpret_cast<uint2*>(cg)[t] = make_uint2(0,0);
        reinterpret_cast<float2*>(sp)[t] = make_float2(0.f,0.f);
        reinterpret_cast<float2*>(sg)[t] = make_float2(0.f,0.f);
        __shared__ double dsm[32];
        #pragma unroll
        for (int o = 16; o; o >>= 1) acc += __shfl_xor_sync(0xffffffffu, acc, o);
        if (lane == 0) dsm[w] = acc;
        __syncthreads();
        if (w == 0) {
            acc = dsm[lane];
            #pragma unroll
            for (int o = 16; o; o >>= 1) acc += __shfl_xor_sync(0xffffffffu, acc, o);
            if (t == 0) g_emd[b] = acc;
        }
    } else if (bx < 40) {
        uint4* m1v = reinterpret_cast<uint4*>(g_m1);
        float s = 0.f;
        for (int i = (bx-32)*1024 + t; i < B_*N_/4; i += 8*1024) {
            uint4 v = m1v[i];
            s += sqrtf(mindec(v.x)) + sqrtf(mindec(v.y))
               + sqrtf(mindec(v.z)) + sqrtf(mindec(v.w));
            m1v[i] = make_uint4(0,0,0,0);
        }
        s = blockReduceSum(s);
        if (t == 0) atomicAdd(&g_s1, (double)s);
    } else {
        uint4* m2v = reinterpret_cast<uint4*>(g_m2);
        float s = 0.f;
        for (int i = (bx-40)*1024 + t; i < N_*N_/4; i += 248*1024) {
            uint4 v = m2v[i];
            s += sqrtf(mindec(v.x)) + sqrtf(mindec(v.y))
               + sqrtf(mindec(v.z)) + sqrtf(mindec(v.w));
            m2v[i] = make_uint4(0,0,0,0);
        }
        s = blockReduceSum(s);
        if (t == 0) atomicAdd(&g_s2, (double)s);
    }

    // last finishing block combines and self-cleans accumulators
    __syncthreads();
    __threadfence();
    __shared__ unsigned amlast;
    if (t == 0) amlast = (atomicAdd(&g_done, 1u) == 287u) ? 1u : 0u;
    __syncthreads();
    if (amlast) {
        if (t < B_) {
            double mae  = g_mae / (double)TOT;
            double cham = g_s1 / (double)(B_*N_) + g_s2 / (double)(N_*N_);
            out[t] = (float)(mae + cham + g_emd[t] / (double)NDF);
        }
        __syncthreads();
        if (t == 0) { g_mae = 0.0; g_s1 = 0.0; g_s2 = 0.0; g_done = 0u; }
    }
}

extern "C" void kernel_launch(void* const* d_in, const int* in_sizes, int n_in,
                              void* d_out, int out_size) {
    const float* pred   = (const float*)d_in[0];
    const float* target = (const float*)d_in[1];
    float* out = (float*)d_out;

    cudaFuncSetAttribute(k_chamfer, cudaFuncAttributeMaxDynamicSharedMemorySize, CHAM_SMEM);
    cudaFuncSetAttribute(k_fused,   cudaFuncAttributeMaxDynamicSharedMemorySize, FUSED_SMEM);

    k_fused<<<512, 512, FUSED_SMEM>>>(pred, target);
    k_chamfer<<<dim3(8, 8, 2), 512, CHAM_SMEM>>>();
    k_post<<<288, 1024>>>(out);
}